// round 1
// baseline (speedup 1.0000x reference)
#include <cuda_runtime.h>

#define NB          4
#define P1_PTS      8192
#define P2_PTS      8192
#define TPB         128
#define SRC_PER_BLK 128
#define TILE        2048
#define NPAIR       (TILE / 2)
#define BLKS_PER_B  (P1_PTS / SRC_PER_BLK)      // 64
#define NBLOCKS     (NB * BLKS_PER_B)           // 256

__device__ float g_partials[NBLOCKS];

__device__ __forceinline__ unsigned long long pack2(float a, float b) {
    unsigned long long r;
    asm("mov.b64 %0, {%1, %2};" : "=l"(r) : "f"(a), "f"(b));
    return r;
}

__device__ __forceinline__ unsigned long long ffma2(unsigned long long a,
                                                    unsigned long long b,
                                                    unsigned long long c) {
    unsigned long long d;
    asm("fma.rn.f32x2 %0, %1, %2, %3;" : "=l"(d) : "l"(a), "l"(b), "l"(c));
    return d;
}

__device__ __forceinline__ void unpack2(unsigned long long v, float& lo, float& hi) {
    asm("mov.b64 {%0, %1}, %2;" : "=f"(lo), "=f"(hi) : "l"(v));
}

__global__ __launch_bounds__(TPB)
void chamfer_main(const float* __restrict__ src, const float* __restrict__ tgt) {
    // Pair-interleaved target tile: per pair p -> [x0,x1,y0,y1,z0,z1,h0,h1]
    __shared__ float sh[TILE * 4];
    __shared__ float red[TPB];

    const int tid   = threadIdx.x;
    const int batch = blockIdx.x / BLKS_PER_B;
    const int sbase = (blockIdx.x % BLKS_PER_B) * SRC_PER_BLK;
    const int sidx  = sbase + tid;

    const float* sp = src + ((long)batch * P1_PTS + sidx) * 3;
    const float sx = sp[0], sy = sp[1], sz = sp[2];
    const float s2 = sx * sx + sy * sy + sz * sz;
    const unsigned long long sxx = pack2(sx, sx);
    const unsigned long long syy = pack2(sy, sy);
    const unsigned long long szz = pack2(sz, sz);

    float mx0 = -3.402823466e38f, mx1 = mx0, mx2 = mx0, mx3 = mx0;

    const float* tb = tgt + (long)batch * P2_PTS * 3;
    const unsigned shbase = (unsigned)__cvta_generic_to_shared(sh);

    for (int t0 = 0; t0 < P2_PTS; t0 += TILE) {
        // ---- load & pack tile: h = -0.5*|t|^2 ----
        for (int j = tid; j < TILE; j += TPB) {
            const float* tp = tb + (t0 + j) * 3;
            float x = tp[0], y = tp[1], z = tp[2];
            float h = -0.5f * (x * x + y * y + z * z);
            int p  = j >> 1;
            int hl = j & 1;
            float* b = sh + p * 8;
            b[0 + hl] = x;
            b[2 + hl] = y;
            b[4 + hl] = z;
            b[6 + hl] = h;
        }
        __syncthreads();

        // ---- inner loop: 2 pairs (4 targets) per iteration, 2 accumulator sets ----
        #pragma unroll 4
        for (int p = 0; p < NPAIR; p += 2) {
            unsigned a0 = shbase + (unsigned)p * 32u;
            unsigned long long xA, yA, zA, hA, xB, yB, zB, hB;
            asm("ld.shared.v2.u64 {%0, %1}, [%2];" : "=l"(xA), "=l"(yA) : "r"(a0));
            asm("ld.shared.v2.u64 {%0, %1}, [%2];" : "=l"(zA), "=l"(hA) : "r"(a0 + 16u));
            asm("ld.shared.v2.u64 {%0, %1}, [%2];" : "=l"(xB), "=l"(yB) : "r"(a0 + 32u));
            asm("ld.shared.v2.u64 {%0, %1}, [%2];" : "=l"(zB), "=l"(hB) : "r"(a0 + 48u));

            unsigned long long mA = ffma2(sxx, xA, ffma2(syy, yA, ffma2(szz, zA, hA)));
            unsigned long long mB = ffma2(sxx, xB, ffma2(syy, yB, ffma2(szz, zB, hB)));

            float l0, h0, l1, h1;
            unpack2(mA, l0, h0);
            unpack2(mB, l1, h1);
            mx0 = fmaxf(mx0, l0);
            mx1 = fmaxf(mx1, h0);
            mx2 = fmaxf(mx2, l1);
            mx3 = fmaxf(mx3, h1);
        }
        __syncthreads();
    }

    const float mx = fmaxf(fmaxf(mx0, mx1), fmaxf(mx2, mx3));
    // nn_d2 = max(0, s2 - 2*mx)   (matches reference clamp of the GEMM-trick)
    const float nn = fmaxf(0.0f, fmaf(-2.0f, mx, s2));

    // deterministic fixed-order block reduction
    red[tid] = nn;
    __syncthreads();
    #pragma unroll
    for (int s = TPB / 2; s > 0; s >>= 1) {
        if (tid < s) red[tid] += red[tid + s];
        __syncthreads();
    }
    if (tid == 0) g_partials[blockIdx.x] = red[0];
}

__global__ __launch_bounds__(NBLOCKS)
void chamfer_final(float* __restrict__ out) {
    __shared__ float red[NBLOCKS];
    const int tid = threadIdx.x;
    red[tid] = g_partials[tid];
    __syncthreads();
    #pragma unroll
    for (int s = NBLOCKS / 2; s > 0; s >>= 1) {
        if (tid < s) red[tid] += red[tid + s];
        __syncthreads();
    }
    if (tid == 0) out[0] = red[0] * (1.0f / (float)NB);
}

extern "C" void kernel_launch(void* const* d_in, const int* in_sizes, int n_in,
                              void* d_out, int out_size) {
    const float* src = (const float*)d_in[0];   // (4, 8192, 3) f32
    const float* tgt = (const float*)d_in[1];   // (4, 8192, 3) f32
    float* out = (float*)d_out;                  // scalar f32

    chamfer_main<<<NBLOCKS, TPB>>>(src, tgt);
    chamfer_final<<<1, NBLOCKS>>>(out);
}

// round 2
// speedup vs baseline: 1.5640x; 1.5640x over previous
#include <cuda_runtime.h>

#define NB          4
#define P1_PTS      8192
#define P2_PTS      8192
#define TPB         128
#define SRC_PER_BLK 256                     // 2 sources per thread
#define TSPLIT      8
#define TILE        (P2_PTS / TSPLIT)       // 1024 targets per block
#define NPAIR       (TILE / 2)              // 512
#define CHUNKS_PER_B (P1_PTS / SRC_PER_BLK) // 32
#define NCHUNK      (NB * CHUNKS_PER_B)     // 128
#define NBLOCKS     (NCHUNK * TSPLIT)       // 1024
#define NSRC_TOT    (NB * P1_PTS)           // 32768
#define NEG_INF     (-3.402823466e38f)

__device__ float g_pmax[TSPLIT * NSRC_TOT]; // [split][global_src], 1 MB
__device__ float g_sums[NCHUNK];

__device__ __forceinline__ unsigned long long pack2(float a, float b) {
    unsigned long long r;
    asm("mov.b64 %0, {%1, %2};" : "=l"(r) : "f"(a), "f"(b));
    return r;
}
__device__ __forceinline__ unsigned long long ffma2(unsigned long long a,
                                                    unsigned long long b,
                                                    unsigned long long c) {
    unsigned long long d;
    asm("fma.rn.f32x2 %0, %1, %2, %3;" : "=l"(d) : "l"(a), "l"(b), "l"(c));
    return d;
}
__device__ __forceinline__ void unpack2(unsigned long long v, float& lo, float& hi) {
    asm("mov.b64 {%0, %1}, %2;" : "=f"(lo), "=f"(hi) : "l"(v));
}

__global__ __launch_bounds__(TPB, 8)
void chamfer_main(const float* __restrict__ src, const float* __restrict__ tgt) {
    // Pair-interleaved target tile: pair p -> [x0,x1, y0,y1, z0,z1, h0,h1]
    __shared__ float sh[TILE * 4];          // 16 KB

    const int tid   = threadIdx.x;
    const int chunk = blockIdx.x >> 3;      // 0..127
    const int split = blockIdx.x & 7;       // 0..7
    const int batch = chunk >> 5;           // 32 chunks per batch
    const int sbase = (chunk & 31) * SRC_PER_BLK;

    // ---- load & pack this block's 1024-target slice ----
    const float* tb = tgt + ((long)batch * P2_PTS + (long)split * TILE) * 3;
    for (int j = tid; j < TILE; j += TPB) {
        float x = tb[j * 3 + 0];
        float y = tb[j * 3 + 1];
        float z = tb[j * 3 + 2];
        float h = -0.5f * (x * x + y * y + z * z);
        float* b = sh + (j >> 1) * 8;
        int hl = j & 1;
        b[0 + hl] = x;
        b[2 + hl] = y;
        b[4 + hl] = z;
        b[6 + hl] = h;
    }

    // ---- two source points per thread ----
    const float* sp0 = src + ((long)batch * P1_PTS + sbase + tid) * 3;
    const float sx0 = sp0[0], sy0 = sp0[1], sz0 = sp0[2];
    const float* sp1 = sp0 + TPB * 3;
    const float sx1 = sp1[0], sy1 = sp1[1], sz1 = sp1[2];

    const unsigned long long X0 = pack2(sx0, sx0), Y0 = pack2(sy0, sy0), Z0 = pack2(sz0, sz0);
    const unsigned long long X1 = pack2(sx1, sx1), Y1 = pack2(sy1, sy1), Z1 = pack2(sz1, sz1);

    float a00 = NEG_INF, a01 = NEG_INF, a02 = NEG_INF, a03 = NEG_INF;
    float a10 = NEG_INF, a11 = NEG_INF, a12 = NEG_INF, a13 = NEG_INF;

    __syncthreads();

    const unsigned shb = (unsigned)__cvta_generic_to_shared(sh);

    // ---- inner loop: 2 target-pairs (4 targets) x 2 sources per iteration ----
    #pragma unroll 4
    for (int p = 0; p < NPAIR; p += 2) {
        unsigned a0 = shb + (unsigned)p * 32u;
        unsigned long long xA, yA, zA, hA, xB, yB, zB, hB;
        asm("ld.shared.v2.u64 {%0, %1}, [%2];" : "=l"(xA), "=l"(yA) : "r"(a0));
        asm("ld.shared.v2.u64 {%0, %1}, [%2];" : "=l"(zA), "=l"(hA) : "r"(a0 + 16u));
        asm("ld.shared.v2.u64 {%0, %1}, [%2];" : "=l"(xB), "=l"(yB) : "r"(a0 + 32u));
        asm("ld.shared.v2.u64 {%0, %1}, [%2];" : "=l"(zB), "=l"(hB) : "r"(a0 + 48u));

        unsigned long long mA0 = ffma2(X0, xA, ffma2(Y0, yA, ffma2(Z0, zA, hA)));
        unsigned long long mB0 = ffma2(X0, xB, ffma2(Y0, yB, ffma2(Z0, zB, hB)));
        unsigned long long mA1 = ffma2(X1, xA, ffma2(Y1, yA, ffma2(Z1, zA, hA)));
        unsigned long long mB1 = ffma2(X1, xB, ffma2(Y1, yB, ffma2(Z1, zB, hB)));

        float l, h;
        unpack2(mA0, l, h); a00 = fmaxf(a00, l); a01 = fmaxf(a01, h);
        unpack2(mB0, l, h); a02 = fmaxf(a02, l); a03 = fmaxf(a03, h);
        unpack2(mA1, l, h); a10 = fmaxf(a10, l); a11 = fmaxf(a11, h);
        unpack2(mB1, l, h); a12 = fmaxf(a12, l); a13 = fmaxf(a13, h);
    }

    const int gsrc = batch * P1_PTS + sbase + tid;
    g_pmax[split * NSRC_TOT + gsrc]       = fmaxf(fmaxf(a00, a01), fmaxf(a02, a03));
    g_pmax[split * NSRC_TOT + gsrc + TPB] = fmaxf(fmaxf(a10, a11), fmaxf(a12, a13));
}

__global__ __launch_bounds__(SRC_PER_BLK)
void chamfer_reduce(const float* __restrict__ src) {
    __shared__ float red[SRC_PER_BLK];
    const int tid  = threadIdx.x;
    const int gsrc = blockIdx.x * SRC_PER_BLK + tid;

    float m = NEG_INF;
    #pragma unroll
    for (int s = 0; s < TSPLIT; s++)
        m = fmaxf(m, g_pmax[s * NSRC_TOT + gsrc]);

    const float* sp = src + (long)gsrc * 3;
    const float sx = sp[0], sy = sp[1], sz = sp[2];
    const float s2 = sx * sx + sy * sy + sz * sz;
    const float nn = fmaxf(0.0f, fmaf(-2.0f, m, s2));

    red[tid] = nn;
    __syncthreads();
    #pragma unroll
    for (int s = SRC_PER_BLK / 2; s > 0; s >>= 1) {
        if (tid < s) red[tid] += red[tid + s];
        __syncthreads();
    }
    if (tid == 0) g_sums[blockIdx.x] = red[0];
}

__global__ __launch_bounds__(NCHUNK)
void chamfer_final(float* __restrict__ out) {
    __shared__ float red[NCHUNK];
    const int tid = threadIdx.x;
    red[tid] = g_sums[tid];
    __syncthreads();
    #pragma unroll
    for (int s = NCHUNK / 2; s > 0; s >>= 1) {
        if (tid < s) red[tid] += red[tid + s];
        __syncthreads();
    }
    if (tid == 0) out[0] = red[0] * (1.0f / (float)NB);
}

extern "C" void kernel_launch(void* const* d_in, const int* in_sizes, int n_in,
                              void* d_out, int out_size) {
    const float* src = (const float*)d_in[0];   // (4, 8192, 3) f32
    const float* tgt = (const float*)d_in[1];   // (4, 8192, 3) f32
    float* out = (float*)d_out;                  // scalar f32

    chamfer_main<<<NBLOCKS, TPB>>>(src, tgt);
    chamfer_reduce<<<NCHUNK, SRC_PER_BLK>>>(src);
    chamfer_final<<<1, NCHUNK>>>(out);
}

// round 3
// speedup vs baseline: 1.7668x; 1.1297x over previous
#include <cuda_runtime.h>

#define NB          4
#define P1_PTS      8192
#define P2_PTS      8192
#define TPB         128
#define NSRC        4                        // sources per thread
#define SRC_PER_BLK (TPB * NSRC)             // 512
#define TSPLIT      16
#define TILE        (P2_PTS / TSPLIT)        // 512 targets per block
#define NPAIR       (TILE / 2)               // 256
#define CHUNKS_PER_B (P1_PTS / SRC_PER_BLK)  // 16
#define NCHUNK      (NB * CHUNKS_PER_B)      // 64
#define NBLOCKS     (NCHUNK * TSPLIT)        // 1024
#define NSRC_TOT    (NB * P1_PTS)            // 32768
#define NEG_INF     (-3.402823466e38f)

#define RED_TPB     256
#define RED_BLKS    (NSRC_TOT / RED_TPB)     // 128

__device__ float g_pmax[TSPLIT * NSRC_TOT];  // 2 MB
__device__ float g_sums[RED_BLKS];

__device__ __forceinline__ unsigned long long pack2(float a, float b) {
    unsigned long long r;
    asm("mov.b64 %0, {%1, %2};" : "=l"(r) : "f"(a), "f"(b));
    return r;
}
__device__ __forceinline__ unsigned long long ffma2(unsigned long long a,
                                                    unsigned long long b,
                                                    unsigned long long c) {
    unsigned long long d;
    asm("fma.rn.f32x2 %0, %1, %2, %3;" : "=l"(d) : "l"(a), "l"(b), "l"(c));
    return d;
}
__device__ __forceinline__ void unpack2(unsigned long long v, float& lo, float& hi) {
    asm("mov.b64 {%0, %1}, %2;" : "=f"(lo), "=f"(hi) : "l"(v));
}

__global__ __launch_bounds__(TPB, 8)
void chamfer_main(const float* __restrict__ src, const float* __restrict__ tgt) {
    // Pair-interleaved target tile: pair p -> [x0,x1, y0,y1, z0,z1, h0,h1]
    __shared__ float sh[TILE * 4];           // 8 KB

    const int tid   = threadIdx.x;
    const int chunk = blockIdx.x >> 4;       // 0..63
    const int split = blockIdx.x & 15;       // 0..15
    const int batch = chunk >> 4;            // 16 chunks per batch
    const int sbase = (chunk & 15) * SRC_PER_BLK;

    // ---- load & pack this block's 512-target slice ----
    const float* tb = tgt + ((long)batch * P2_PTS + (long)split * TILE) * 3;
    for (int j = tid; j < TILE; j += TPB) {
        float x = tb[j * 3 + 0];
        float y = tb[j * 3 + 1];
        float z = tb[j * 3 + 2];
        float h = -0.5f * (x * x + y * y + z * z);
        float* b = sh + (j >> 1) * 8;
        int hl = j & 1;
        b[0 + hl] = x;
        b[2 + hl] = y;
        b[4 + hl] = z;
        b[6 + hl] = h;
    }

    // ---- four source points per thread ----
    unsigned long long X[NSRC], Y[NSRC], Z[NSRC];
    const float* sp = src + ((long)batch * P1_PTS + sbase + tid) * 3;
    #pragma unroll
    for (int s = 0; s < NSRC; s++) {
        float x = sp[s * TPB * 3 + 0];
        float y = sp[s * TPB * 3 + 1];
        float z = sp[s * TPB * 3 + 2];
        X[s] = pack2(x, x);
        Y[s] = pack2(y, y);
        Z[s] = pack2(z, z);
    }

    float acc0[NSRC], acc1[NSRC];
    #pragma unroll
    for (int s = 0; s < NSRC; s++) { acc0[s] = NEG_INF; acc1[s] = NEG_INF; }

    __syncthreads();

    const unsigned shb = (unsigned)__cvta_generic_to_shared(sh);

    // ---- inner loop: 2 target-pairs (4 targets) x 4 sources = 16 evals/iter ----
    #pragma unroll 4
    for (int p = 0; p < NPAIR; p += 2) {
        unsigned a0 = shb + (unsigned)p * 32u;
        unsigned long long xA, yA, zA, hA, xB, yB, zB, hB;
        asm("ld.shared.v2.u64 {%0, %1}, [%2];" : "=l"(xA), "=l"(yA) : "r"(a0));
        asm("ld.shared.v2.u64 {%0, %1}, [%2];" : "=l"(zA), "=l"(hA) : "r"(a0 + 16u));
        asm("ld.shared.v2.u64 {%0, %1}, [%2];" : "=l"(xB), "=l"(yB) : "r"(a0 + 32u));
        asm("ld.shared.v2.u64 {%0, %1}, [%2];" : "=l"(zB), "=l"(hB) : "r"(a0 + 48u));

        #pragma unroll
        for (int s = 0; s < NSRC; s++) {
            unsigned long long mA = ffma2(X[s], xA, ffma2(Y[s], yA, ffma2(Z[s], zA, hA)));
            unsigned long long mB = ffma2(X[s], xB, ffma2(Y[s], yB, ffma2(Z[s], zB, hB)));
            float lA, hA2, lB, hB2;
            unpack2(mA, lA, hA2);
            unpack2(mB, lB, hB2);
            acc0[s] = fmaxf(acc0[s], fmaxf(lA, lB));
            acc1[s] = fmaxf(acc1[s], fmaxf(hA2, hB2));
        }
    }

    const int gsrc = batch * P1_PTS + sbase + tid;
    #pragma unroll
    for (int s = 0; s < NSRC; s++)
        g_pmax[split * NSRC_TOT + gsrc + s * TPB] = fmaxf(acc0[s], acc1[s]);
}

__global__ __launch_bounds__(RED_TPB)
void chamfer_reduce(const float* __restrict__ src) {
    __shared__ float red[RED_TPB];
    const int tid  = threadIdx.x;
    const int gsrc = blockIdx.x * RED_TPB + tid;

    float m = NEG_INF;
    #pragma unroll
    for (int s = 0; s < TSPLIT; s++)
        m = fmaxf(m, g_pmax[s * NSRC_TOT + gsrc]);

    const float* sp = src + (long)gsrc * 3;
    const float sx = sp[0], sy = sp[1], sz = sp[2];
    const float s2 = sx * sx + sy * sy + sz * sz;
    const float nn = fmaxf(0.0f, fmaf(-2.0f, m, s2));

    red[tid] = nn;
    __syncthreads();
    #pragma unroll
    for (int s = RED_TPB / 2; s > 0; s >>= 1) {
        if (tid < s) red[tid] += red[tid + s];
        __syncthreads();
    }
    if (tid == 0) g_sums[blockIdx.x] = red[0];
}

__global__ __launch_bounds__(RED_BLKS)
void chamfer_final(float* __restrict__ out) {
    __shared__ float red[RED_BLKS];
    const int tid = threadIdx.x;
    red[tid] = g_sums[tid];
    __syncthreads();
    #pragma unroll
    for (int s = RED_BLKS / 2; s > 0; s >>= 1) {
        if (tid < s) red[tid] += red[tid + s];
        __syncthreads();
    }
    if (tid == 0) out[0] = red[0] * (1.0f / (float)NB);
}

extern "C" void kernel_launch(void* const* d_in, const int* in_sizes, int n_in,
                              void* d_out, int out_size) {
    const float* src = (const float*)d_in[0];   // (4, 8192, 3) f32
    const float* tgt = (const float*)d_in[1];   // (4, 8192, 3) f32
    float* out = (float*)d_out;                  // scalar f32

    chamfer_main<<<NBLOCKS, TPB>>>(src, tgt);
    chamfer_reduce<<<RED_BLKS, RED_TPB>>>(src);
    chamfer_final<<<1, RED_BLKS>>>(out);
}